// round 6
// baseline (speedup 1.0000x reference)
#include <cuda_runtime.h>
#include <cuda_bf16.h>
#include <cstdint>

#define NUM_LEVELS 32
#define SCALE_F 0.15f
#define BATCH 8
#define SEQ 8192
#define DIM 1024
#define NTOK (BATCH * SEQ)
#define BIGV 100000
#define ROW_BYTES (DIM * 4)          // 4096 bytes per output row

// scratch (alloc-free rule: __device__ globals)
__device__ unsigned char g_levels[NTOK];

// ---------------------------------------------------------------------------
// Composite algebra: f(x) = clip(x + a, l, h) is closed under composition.
// ---------------------------------------------------------------------------
struct Cmp { int a, l, h; };

__device__ __forceinline__ Cmp comp2(Cmp p, Cmp q) {
    Cmp r;
    r.a = p.a + q.a;
    r.l = min(max(p.l + q.a, q.l), q.h);
    r.h = min(max(p.h + q.a, q.l), q.h);
    return r;
}

__device__ __forceinline__ int delta_of(int t) {
    return (int)((t == 40) | (t == 91) | (t == 123))
         - (int)((t == 41) | (t == 93) | (t == 125));
}

__device__ __forceinline__ Cmp warp_incl_scan(Cmp c, int lane) {
#pragma unroll
    for (int off = 1; off < 32; off <<= 1) {
        int pa = __shfl_up_sync(0xFFFFFFFFu, c.a, off);
        int pl = __shfl_up_sync(0xFFFFFFFFu, c.l, off);
        int ph = __shfl_up_sync(0xFFFFFFFFu, c.h, off);
        if (lane >= off) { Cmp p = {pa, pl, ph}; c = comp2(p, c); }
    }
    return c;
}

// ---------------------------------------------------------------------------
// Levels: 8 blocks (one per batch row) x 1024 threads, 8 tokens/thread.
// Shfl warp scan -> one smem stage -> per-thread prefix. 2 __syncthreads.
// ---------------------------------------------------------------------------
__global__ __launch_bounds__(1024) void levels_kernel(const int* __restrict__ tok) {
    __shared__ Cmp wc[32];
    __shared__ Cmp we[32];
    const int b = blockIdx.x;
    const int tid = threadIdx.x;
    const int lane = tid & 31, warp = tid >> 5;

    const int base = b * SEQ + tid * 8;
    const int4 t0 = *(const int4*)(tok + base);
    const int4 t1 = *(const int4*)(tok + base + 4);

    int d[8];
    d[0] = delta_of(t0.x); d[1] = delta_of(t0.y);
    d[2] = delta_of(t0.z); d[3] = delta_of(t0.w);
    d[4] = delta_of(t1.x); d[5] = delta_of(t1.y);
    d[6] = delta_of(t1.z); d[7] = delta_of(t1.w);

    Cmp c = {0, -BIGV, BIGV};
#pragma unroll
    for (int i = 0; i < 8; i++) {
        c.a += d[i];
        c.l = min(max(c.l + d[i], 0), NUM_LEVELS - 1);
        c.h = min(max(c.h + d[i], 0), NUM_LEVELS - 1);
    }

    const Cmp incl = warp_incl_scan(c, lane);
    if (lane == 31) wc[warp] = incl;
    __syncthreads();

    if (warp == 0) {
        Cmp v = wc[lane];
        v = warp_incl_scan(v, lane);
        Cmp e;
        e.a = __shfl_up_sync(0xFFFFFFFFu, v.a, 1);
        e.l = __shfl_up_sync(0xFFFFFFFFu, v.l, 1);
        e.h = __shfl_up_sync(0xFFFFFFFFu, v.h, 1);
        if (lane == 0) { e.a = 0; e.l = -BIGV; e.h = BIGV; }
        we[lane] = e;
    }
    __syncthreads();

    Cmp lex;
    lex.a = __shfl_up_sync(0xFFFFFFFFu, incl.a, 1);
    lex.l = __shfl_up_sync(0xFFFFFFFFu, incl.l, 1);
    lex.h = __shfl_up_sync(0xFFFFFFFFu, incl.h, 1);
    if (lane == 0) { lex.a = 0; lex.l = -BIGV; lex.h = BIGV; }

    const Cmp pre = comp2(we[warp], lex);
    int x = min(max(pre.a, pre.l), pre.h);

    unsigned int p0 = 0, p1 = 0;
#pragma unroll
    for (int i = 0; i < 4; i++) {
        x = min(max(x + d[i], 0), NUM_LEVELS - 1);
        p0 |= ((unsigned int)x) << (i * 8);
    }
#pragma unroll
    for (int i = 4; i < 8; i++) {
        x = min(max(x + d[i], 0), NUM_LEVELS - 1);
        p1 |= ((unsigned int)x) << ((i - 4) * 8);
    }
    *(uint2*)(g_levels + base) = make_uint2(p0, p1);
}

// ---------------------------------------------------------------------------
// Gather via bulk-async (TMA) SMEM->GMEM copies.
// Pre-scaled table (32 x 4KB = 128 KB) in dynamic smem. Block b owns tokens
// {b + 148k}. Each active thread issues ONE 4 KB cp.async.bulk from the
// level's table row straight to the output row: no LDS, no STG, no regs.
// ---------------------------------------------------------------------------
__global__ __launch_bounds__(512) void gather_tma(const float* __restrict__ emb,
                                                  float* __restrict__ out) {
    extern __shared__ float semb[];
    const int tid = threadIdx.x;

    // load + scale table into smem
    const float4* __restrict__ e4 = (const float4*)emb;
    float4* s4 = (float4*)semb;
    for (int i = tid; i < NUM_LEVELS * DIM / 4; i += 512) {
        float4 v = e4[i];
        v.x *= SCALE_F; v.y *= SCALE_F; v.z *= SCALE_F; v.w *= SCALE_F;
        s4[i] = v;
    }
    // order generic smem writes before async-proxy (TMA) reads
    asm volatile("fence.proxy.async.shared::cta;" ::: "memory");
    __syncthreads();

    // smem base as 32-bit shared address
    uint32_t sbase;
    asm("{ .reg .u64 t; cvta.to.shared.u64 t, %1; cvt.u32.u64 %0, t; }"
        : "=r"(sbase) : "l"(semb));

    const int token = blockIdx.x + 148 * tid;   // block-strided token ownership
    if (tid < 443 && token < NTOK) {
        const int lvl = (int)g_levels[token];
        const uint32_t src = sbase + (uint32_t)lvl * ROW_BYTES;
        float* dst = out + (size_t)token * DIM;
        asm volatile("cp.async.bulk.global.shared::cta.bulk_group [%0], [%1], %2;"
                     :: "l"(dst), "r"(src), "r"(ROW_BYTES) : "memory");
        asm volatile("cp.async.bulk.commit_group;" ::: "memory");
        asm volatile("cp.async.bulk.wait_group 0;" ::: "memory");
    }
}

extern "C" void kernel_launch(void* const* d_in, const int* in_sizes, int n_in,
                              void* d_out, int out_size) {
    const int* token_ids = (const int*)d_in[0];
    const float* level_emb = (const float*)d_in[1];
    float* out = (float*)d_out;

    cudaFuncSetAttribute(gather_tma,
                         cudaFuncAttributeMaxDynamicSharedMemorySize,
                         NUM_LEVELS * DIM * (int)sizeof(float));

    levels_kernel<<<BATCH, 1024>>>(token_ids);
    gather_tma<<<148, 512, NUM_LEVELS * DIM * sizeof(float)>>>(level_emb, out);
}

// round 7
// speedup vs baseline: 1.1142x; 1.1142x over previous
#include <cuda_runtime.h>
#include <cuda_bf16.h>
#include <cstdint>

#define NUM_LEVELS 32
#define SCALE_F 0.15f
#define BATCH 8
#define SEQ 8192
#define DIM 1024
#define NTOK (BATCH * SEQ)
#define NCHUNK (NTOK / 64)
#define BIGV 100000

// scratch (alloc-free rule: __device__ globals)
__device__ unsigned char g_levels[NTOK];
__device__ unsigned int g_ready;   // monotonic across graph replays; +8 per run

// ---------------------------------------------------------------------------
// Composite algebra: f(x) = clip(x + a, l, h), closed under composition.
// ---------------------------------------------------------------------------
struct Cmp { int a, l, h; };

__device__ __forceinline__ Cmp comp2(Cmp p, Cmp q) {
    Cmp r;
    r.a = p.a + q.a;
    r.l = min(max(p.l + q.a, q.l), q.h);
    r.h = min(max(p.h + q.a, q.l), q.h);
    return r;
}

__device__ __forceinline__ int delta_of(int t) {
    return (int)((t == 40) | (t == 91) | (t == 123))
         - (int)((t == 41) | (t == 93) | (t == 125));
}

__device__ __forceinline__ Cmp warp_incl_scan(Cmp c, int lane) {
#pragma unroll
    for (int off = 1; off < 32; off <<= 1) {
        int pa = __shfl_up_sync(0xFFFFFFFFu, c.a, off);
        int pl = __shfl_up_sync(0xFFFFFFFFu, c.l, off);
        int ph = __shfl_up_sync(0xFFFFFFFFu, c.h, off);
        if (lane >= off) { Cmp p = {pa, pl, ph}; c = comp2(p, c); }
    }
    return c;
}

// Levels scan for row b, executed by one 1024-thread block (8 tokens/thread).
__device__ __forceinline__ void do_levels(const int* __restrict__ tok, int b,
                                          Cmp* wc, Cmp* we) {
    const int tid = threadIdx.x;
    const int lane = tid & 31, warp = tid >> 5;

    const int base = b * SEQ + tid * 8;
    const int4 t0 = *(const int4*)(tok + base);
    const int4 t1 = *(const int4*)(tok + base + 4);

    int d[8];
    d[0] = delta_of(t0.x); d[1] = delta_of(t0.y);
    d[2] = delta_of(t0.z); d[3] = delta_of(t0.w);
    d[4] = delta_of(t1.x); d[5] = delta_of(t1.y);
    d[6] = delta_of(t1.z); d[7] = delta_of(t1.w);

    Cmp c = {0, -BIGV, BIGV};
#pragma unroll
    for (int i = 0; i < 8; i++) {
        c.a += d[i];
        c.l = min(max(c.l + d[i], 0), NUM_LEVELS - 1);
        c.h = min(max(c.h + d[i], 0), NUM_LEVELS - 1);
    }

    const Cmp incl = warp_incl_scan(c, lane);
    if (lane == 31) wc[warp] = incl;
    __syncthreads();

    if (warp == 0) {
        Cmp v = wc[lane];
        v = warp_incl_scan(v, lane);
        Cmp e;
        e.a = __shfl_up_sync(0xFFFFFFFFu, v.a, 1);
        e.l = __shfl_up_sync(0xFFFFFFFFu, v.l, 1);
        e.h = __shfl_up_sync(0xFFFFFFFFu, v.h, 1);
        if (lane == 0) { e.a = 0; e.l = -BIGV; e.h = BIGV; }
        we[lane] = e;
    }
    __syncthreads();

    Cmp lex;
    lex.a = __shfl_up_sync(0xFFFFFFFFu, incl.a, 1);
    lex.l = __shfl_up_sync(0xFFFFFFFFu, incl.l, 1);
    lex.h = __shfl_up_sync(0xFFFFFFFFu, incl.h, 1);
    if (lane == 0) { lex.a = 0; lex.l = -BIGV; lex.h = BIGV; }

    const Cmp pre = comp2(we[warp], lex);
    int x = min(max(pre.a, pre.l), pre.h);

    unsigned int p0 = 0, p1 = 0;
#pragma unroll
    for (int i = 0; i < 4; i++) {
        x = min(max(x + d[i], 0), NUM_LEVELS - 1);
        p0 |= ((unsigned int)x) << (i * 8);
    }
#pragma unroll
    for (int i = 4; i < 8; i++) {
        x = min(max(x + d[i], 0), NUM_LEVELS - 1);
        p1 |= ((unsigned int)x) << ((i - 4) * 8);
    }
    *(uint2*)(g_levels + base) = make_uint2(p0, p1);
}

// ---------------------------------------------------------------------------
// Fused persistent kernel: 148 blocks x 1024 threads, all co-resident.
// Blocks 0-7: levels for their row, then flag. All blocks: load+scale table
// into smem (overlaps levels), spin until all 8 rows ready, then gather.
// Gather: per 64-token chunk, hoisted uint4 level load + 16 independent
// LDS.128 -> STG.128(streaming) pairs (the measured-best R5 datapath).
// ---------------------------------------------------------------------------
__global__ __launch_bounds__(1024) void fused_kernel(const int* __restrict__ tok,
                                                     const float* __restrict__ emb,
                                                     float4* __restrict__ out) {
    extern __shared__ float semb[];
    __shared__ Cmp wc[32];
    __shared__ Cmp we[32];
    const int b = blockIdx.x;
    const int tid = threadIdx.x;

    // snapshot the ready-counter target for THIS run (monotonic across replays)
    const unsigned int target = (*(volatile unsigned int*)&g_ready / 8u) * 8u + 8u;

    if (b < 8) {
        do_levels(tok, b, wc, we);
        __syncthreads();
        if (tid == 0) {
            __threadfence();
            atomicAdd(&g_ready, 1u);
        }
    }

    // load + scale table into smem (overlaps the levels work on blocks 8..147)
    const float4* __restrict__ e4 = (const float4*)emb;
    float4* s4 = (float4*)semb;
    for (int i = tid; i < NUM_LEVELS * DIM / 4; i += 1024) {
        float4 v = e4[i];
        v.x *= SCALE_F; v.y *= SCALE_F; v.z *= SCALE_F; v.w *= SCALE_F;
        s4[i] = v;
    }
    __syncthreads();

    // wait until all 8 rows' levels for this run are published.
    // (re-runs racing with identical recomputed g_levels values are benign:
    //  levels are a pure function of unchanged inputs.)
    if (tid == 0) {
        while (*(volatile unsigned int*)&g_ready < target) { }
        __threadfence();
    }
    __syncthreads();

    // static chunk schedule: levels blocks (0-7) and the last 4 get 6 chunks,
    // blocks 8-143 get 7.  48 + 136*7 + 4*6 = 1024.
    int start, count;
    if (b < 8)        { start = b * 6;                count = 6; }
    else if (b < 144) { start = 48 + (b - 8) * 7;     count = 7; }
    else              { start = 1000 + (b - 144) * 6; count = 6; }

    const int g = tid >> 8;    // 16-token quarter of the chunk
    const int j = tid & 255;   // float4 index within the row

    for (int i = 0; i < count; i++) {
        const int c = start + i;
        const uint4 lv = *(const uint4*)(g_levels + c * 64 + g * 16);
        const unsigned int w[4] = {lv.x, lv.y, lv.z, lv.w};
        float4* obase = out + (size_t)(c * 64 + g * 16) * (DIM / 4) + j;
#pragma unroll
        for (int k = 0; k < 16; k++) {
            const int lvl = (int)((w[k >> 2] >> ((k & 3) * 8)) & 0xFF);
            const float4 v = s4[lvl * (DIM / 4) + j];
            __stcs(obase + (size_t)k * (DIM / 4), v);
        }
    }
}

extern "C" void kernel_launch(void* const* d_in, const int* in_sizes, int n_in,
                              void* d_out, int out_size) {
    const int* token_ids = (const int*)d_in[0];
    const float* level_emb = (const float*)d_in[1];
    float4* out = (float4*)d_out;

    cudaFuncSetAttribute(fused_kernel,
                         cudaFuncAttributeMaxDynamicSharedMemorySize,
                         NUM_LEVELS * DIM * (int)sizeof(float));

    fused_kernel<<<148, 1024, NUM_LEVELS * DIM * sizeof(float)>>>(token_ids, level_emb, out);
}